// round 2
// baseline (speedup 1.0000x reference)
#include <cuda_runtime.h>
#include <math.h>

#define SS 128
#define BB 32
#define VV 32000
#define NINP 1024
#define NHID 1024
#define NHEADS 16
#define HD 64

// ---------------- device scratch (no allocs allowed) ----------------
static __device__ float g_emb[(size_t)SS * BB * NINP];      // tf32-rounded embeddings
static __device__ float g_xbuf[BB * 3072];                  // [hidden|q|attn], tf32-rounded
static __device__ float g_kcache[(size_t)(SS + 1) * BB * NHID];
static __device__ float g_vcache[(size_t)(SS + 1) * BB * NHID];
static __device__ float g_inter[BB * 4096];                 // tf32-rounded
static __device__ float g_part[4 * BB * 4096];              // split-K partials

// ---------------- helpers ----------------
__device__ __forceinline__ float tf32r(float x) {
    unsigned u;
    asm("cvt.rna.tf32.f32 %0, %1;" : "=r"(u) : "f"(x));
    return __uint_as_float(u);
}

__device__ __forceinline__ void mma8(float* c, float a0, float a1, float a2, float a3,
                                     float b0, float b1) {
    asm volatile(
        "mma.sync.aligned.m16n8k8.row.col.f32.tf32.tf32.f32 "
        "{%0,%1,%2,%3}, {%4,%5,%6,%7}, {%8,%9}, {%0,%1,%2,%3};"
        : "+f"(c[0]), "+f"(c[1]), "+f"(c[2]), "+f"(c[3])
        : "r"(__float_as_uint(a0)), "r"(__float_as_uint(a1)),
          "r"(__float_as_uint(a2)), "r"(__float_as_uint(a3)),
          "r"(__float_as_uint(b0)), "r"(__float_as_uint(b1)));
}

__device__ __forceinline__ float blockReduceSum(float v, float* sc) {
    int lane = threadIdx.x & 31, w = threadIdx.x >> 5;
#pragma unroll
    for (int o = 16; o; o >>= 1) v += __shfl_down_sync(0xffffffffu, v, o);
    if (lane == 0) sc[w] = v;
    __syncthreads();
    if (threadIdx.x < 32) {
        float r = (threadIdx.x < 8) ? sc[threadIdx.x] : 0.f;
#pragma unroll
        for (int o = 4; o; o >>= 1) r += __shfl_down_sync(0xffffffffu, r, o);
        if (threadIdx.x == 0) sc[0] = r;
    }
    __syncthreads();
    float out = sc[0];
    __syncthreads();
    return out;
}

// ---------------- setup kernels ----------------
__global__ void k_init(const float* __restrict__ hinit, const float* __restrict__ kinit,
                       const float* __restrict__ vinit, float* __restrict__ states_full) {
    int b = blockIdx.x, tid = threadIdx.x;
#pragma unroll
    for (int it = 0; it < 4; it++) {
        int c = tid + it * 256;
        float h = hinit[b * NHID + c];
        g_xbuf[b * 3072 + c] = tf32r(h);
        states_full[b * NHID + c] = h;
        g_kcache[b * NHID + c] = kinit[b * NHID + c];
        g_vcache[b * NHID + c] = vinit[b * NHID + c];
    }
}

__global__ void k_embed(const int* __restrict__ obs, const float* __restrict__ enc_w) {
    int idx = blockIdx.x;  // s*B + b
    int row = obs[idx];
    int tid = threadIdx.x;
#pragma unroll
    for (int it = 0; it < 4; it++) {
        int c = tid + it * 256;
        g_emb[(size_t)idx * NINP + c] = tf32r(enc_w[(size_t)row * NINP + c]);
    }
}

// ---------------- step GEMM: out[b,n] = sum_k x[b,k]*W[n,k]  (M=32, split-K x4) ----------------
// x cols: [0,ecols) from g_emb(step row), rest from xr (g_xbuf or g_inter)
__global__ __launch_bounds__(256) void k_gemm_step(int estep, int xsel,
                                                   const float* __restrict__ W,
                                                   int K, int klen, int N, int permute) {
    __shared__ float xs[32][33];
    __shared__ float ws[64][33];
    const float* xe = g_emb + (size_t)(estep > 0 ? estep : 0) * BB * NINP;
    int ecols = (estep >= 0) ? NINP : 0;
    const float* xr = xsel ? g_inter : g_xbuf;
    int xstride = xsel ? 4096 : 3072;

    int tid = threadIdx.x;
    int nb = blockIdx.x * 64;
    int k0 = blockIdx.y * klen;
    int w = tid >> 5, lane = tid & 31, gid = lane >> 2, tig = lane & 3;
    float acc0[4] = {0.f, 0.f, 0.f, 0.f};
    float acc1[4] = {0.f, 0.f, 0.f, 0.f};

    for (int kc = k0; kc < k0 + klen; kc += 32) {
#pragma unroll
        for (int it = 0; it < 4; it++) {  // x: 32x32
            int e = tid + it * 256;
            int r = e >> 5, c = e & 31, gc = kc + c;
            float v = (gc < ecols) ? xe[r * NINP + gc] : xr[r * xstride + gc - ecols];
            xs[r][c] = v;
        }
#pragma unroll
        for (int it = 0; it < 8; it++) {  // w: 64x32
            int e = tid + it * 256;
            int r = e >> 5, c = e & 31, gc = kc + c;
            int wc = gc;
            if (permute) wc = (gc < 1024) ? gc : ((gc < 2048) ? gc + 2048 : gc - 1024);
            ws[r][c] = tf32r(W[(size_t)(nb + r) * K + wc]);
        }
        __syncthreads();
#pragma unroll
        for (int ks = 0; ks < 4; ks++) {
            int kk = ks * 8;
            float b0 = ws[w * 8 + gid][kk + tig];
            float b1 = ws[w * 8 + gid][kk + tig + 4];
            float a0 = xs[gid][kk + tig], a1 = xs[gid + 8][kk + tig];
            float a2 = xs[gid][kk + tig + 4], a3 = xs[gid + 8][kk + tig + 4];
            mma8(acc0, a0, a1, a2, a3, b0, b1);
            float c0 = xs[gid + 16][kk + tig], c1 = xs[gid + 24][kk + tig];
            float c2 = xs[gid + 16][kk + tig + 4], c3 = xs[gid + 24][kk + tig + 4];
            mma8(acc1, c0, c1, c2, c3, b0, b1);
        }
        __syncthreads();
    }
    float* p = g_part + (size_t)blockIdx.y * 32 * N;
    int n0 = nb + w * 8 + 2 * tig;
    p[gid * N + n0] = acc0[0];         p[gid * N + n0 + 1] = acc0[1];
    p[(gid + 8) * N + n0] = acc0[2];   p[(gid + 8) * N + n0 + 1] = acc0[3];
    p[(gid + 16) * N + n0] = acc1[0];  p[(gid + 16) * N + n0 + 1] = acc1[1];
    p[(gid + 24) * N + n0] = acc1[2];  p[(gid + 24) * N + n0 + 1] = acc1[3];
}

// ---------------- LN(q)+relu + 16-head attention, one block per batch row ----------------
__global__ void k_ln_q_attn(const float* __restrict__ qb, const float* __restrict__ gg,
                            const float* __restrict__ bb, int step) {
    __shared__ float pre[1024];
    __shared__ float red[32];
    __shared__ float sc[136];
    __shared__ float ored[4][64];
    int b = blockIdx.x, tid = threadIdx.x;

    float s1 = 0.f, s2 = 0.f;
#pragma unroll
    for (int it = 0; it < 4; it++) {
        int c = tid + it * 256;
        float v = g_part[b * 1024 + c] + g_part[32 * 1024 + b * 1024 + c] +
                  g_part[2 * 32 * 1024 + b * 1024 + c] + g_part[3 * 32 * 1024 + b * 1024 + c] +
                  qb[c];
        pre[c] = v;
        s1 += v;
        s2 += v * v;
    }
    s1 = blockReduceSum(s1, red);
    s2 = blockReduceSum(s2, red);
    float mu = s1 * (1.f / 1024.f);
    float var = s2 * (1.f / 1024.f) - mu * mu;
    float rstd = 1.f / sqrtf(var + 1e-5f);
#pragma unroll
    for (int it = 0; it < 4; it++) {
        int c = tid + it * 256;
        float q = (pre[c] - mu) * rstd * gg[c] + bb[c];
        q = fmaxf(q, 0.f);
        pre[c] = q;
        g_xbuf[b * 3072 + 1024 + c] = tf32r(q);
    }
    __syncthreads();

    int L = step + 1;
    int w = tid >> 5, lane = tid & 31;
    for (int h = 0; h < NHEADS; h++) {
        const float* qh = pre + h * HD;
        for (int c = w; c < L; c += 8) {
            const float* kr = g_kcache + ((size_t)c * BB + b) * NHID + h * HD;
            float p = qh[2 * lane] * kr[2 * lane] + qh[2 * lane + 1] * kr[2 * lane + 1];
#pragma unroll
            for (int o = 16; o; o >>= 1) p += __shfl_down_sync(0xffffffffu, p, o);
            if (lane == 0) sc[c] = p * 0.125f;
        }
        __syncthreads();
        // max
        float m = -1e30f;
        for (int c = tid; c < L; c += 256) m = fmaxf(m, sc[c]);
#pragma unroll
        for (int o = 16; o; o >>= 1) m = fmaxf(m, __shfl_down_sync(0xffffffffu, m, o));
        if (lane == 0) red[w] = m;
        __syncthreads();
        if (tid < 32) {
            float r = (tid < 8) ? red[tid] : -1e30f;
#pragma unroll
            for (int o = 4; o; o >>= 1) r = fmaxf(r, __shfl_down_sync(0xffffffffu, r, o));
            if (tid == 0) red[0] = r;
        }
        __syncthreads();
        m = red[0];
        __syncthreads();
        float se = 0.f;
        for (int c = tid; c < L; c += 256) {
            float e = expf(sc[c] - m);
            sc[c] = e;
            se += e;
        }
        se = blockReduceSum(se, red);
        float inv = 1.f / se;
        // weighted sum of V
        int d = tid & 63, cq = tid >> 6;
        float acc = 0.f;
        for (int c = cq; c < L; c += 4)
            acc += sc[c] * g_vcache[((size_t)c * BB + b) * NHID + h * HD + d];
        ored[cq][d] = acc;
        __syncthreads();
        if (tid < 64) {
            float o = (ored[0][tid] + ored[1][tid] + ored[2][tid] + ored[3][tid]) * inv;
            g_xbuf[b * 3072 + 2048 + h * HD + tid] = tf32r(o);
        }
        __syncthreads();
    }
}

// ---------------- LN(int)+relu -> g_inter ----------------
__global__ void k_ln_int(const float* __restrict__ bias, const float* __restrict__ gg,
                         const float* __restrict__ bb) {
    __shared__ float pre[4096];
    __shared__ float red[32];
    int b = blockIdx.x, tid = threadIdx.x;
    float s1 = 0.f, s2 = 0.f;
#pragma unroll
    for (int it = 0; it < 16; it++) {
        int c = tid + it * 256;
        float v = g_part[b * 4096 + c] + g_part[32 * 4096 + b * 4096 + c] +
                  g_part[2 * 32 * 4096 + b * 4096 + c] + g_part[3 * 32 * 4096 + b * 4096 + c] +
                  bias[c];
        pre[c] = v;
        s1 += v;
        s2 += v * v;
    }
    s1 = blockReduceSum(s1, red);
    s2 = blockReduceSum(s2, red);
    float mu = s1 * (1.f / 4096.f);
    float var = s2 * (1.f / 4096.f) - mu * mu;
    float rstd = 1.f / sqrtf(var + 1e-5f);
#pragma unroll
    for (int it = 0; it < 16; it++) {
        int c = tid + it * 256;
        float y = fmaxf((pre[c] - mu) * rstd * gg[c] + bb[c], 0.f);
        g_inter[b * 4096 + c] = tf32r(y);
    }
}

// ---------------- LN(fin)+relu -> split into kcache[i+1], vcache[i+1], hidden/states ----------------
__global__ void k_ln_fin(const float* __restrict__ bias, const float* __restrict__ gg,
                         const float* __restrict__ bb, int step,
                         float* __restrict__ states_full) {
    __shared__ float pre[3072];
    __shared__ float red[32];
    int b = blockIdx.x, tid = threadIdx.x;
    float s1 = 0.f, s2 = 0.f;
#pragma unroll
    for (int it = 0; it < 12; it++) {
        int c = tid + it * 256;
        float v = g_part[b * 3072 + c] + g_part[32 * 3072 + b * 3072 + c] +
                  g_part[2 * 32 * 3072 + b * 3072 + c] + g_part[3 * 32 * 3072 + b * 3072 + c] +
                  bias[c];
        pre[c] = v;
        s1 += v;
        s2 += v * v;
    }
    s1 = blockReduceSum(s1, red);
    s2 = blockReduceSum(s2, red);
    float mu = s1 * (1.f / 3072.f);
    float var = s2 * (1.f / 3072.f) - mu * mu;
    float rstd = 1.f / sqrtf(var + 1e-5f);
#pragma unroll
    for (int it = 0; it < 12; it++) {
        int c = tid + it * 256;
        float y = fmaxf((pre[c] - mu) * rstd * gg[c] + bb[c], 0.f);
        if (c < 1024) {
            g_kcache[((size_t)(step + 1) * BB + b) * NHID + c] = y;
        } else if (c < 2048) {
            g_vcache[((size_t)(step + 1) * BB + b) * NHID + (c - 1024)] = y;
        } else {
            int d = c - 2048;
            states_full[((size_t)(step + 1) * BB + b) * NHID + d] = y;
            g_xbuf[b * 3072 + d] = tf32r(y);
        }
    }
}

// ---------------- decoder GEMM: logits[r,n] = states[r,:]@dec_w[n,:] + dec_b[n] ----------------
__global__ __launch_bounds__(256) void k_dec(const float* __restrict__ A,
                                             const float* __restrict__ Wd,
                                             const float* __restrict__ bias,
                                             float* __restrict__ out) {
    __shared__ float as[64][33];
    __shared__ float bs[64][33];
    int tid = threadIdx.x;
    int nb = blockIdx.x * 64, mb = blockIdx.y * 64;
    int w = tid >> 5, lane = tid & 31, gid = lane >> 2, tig = lane & 3;
    int mw = w & 1, nw = w >> 1;
    float acc[2][2][4] = {};

    for (int kc = 0; kc < 1024; kc += 32) {
#pragma unroll
        for (int it = 0; it < 8; it++) {
            int e = tid + it * 256;
            int r = e >> 5, c = e & 31;
            as[r][c] = tf32r(A[(size_t)(mb + r) * 1024 + kc + c]);
        }
#pragma unroll
        for (int it = 0; it < 8; it++) {
            int e = tid + it * 256;
            int r = e >> 5, c = e & 31;
            bs[r][c] = tf32r(Wd[(size_t)(nb + r) * 1024 + kc + c]);
        }
        __syncthreads();
#pragma unroll
        for (int ks = 0; ks < 4; ks++) {
            int kk = ks * 8;
            float bf[2][2];
#pragma unroll
            for (int nt = 0; nt < 2; nt++) {
                bf[nt][0] = bs[nw * 16 + nt * 8 + gid][kk + tig];
                bf[nt][1] = bs[nw * 16 + nt * 8 + gid][kk + tig + 4];
            }
#pragma unroll
            for (int mt = 0; mt < 2; mt++) {
                int rb = mw * 32 + mt * 16;
                float a0 = as[rb + gid][kk + tig], a1 = as[rb + gid + 8][kk + tig];
                float a2 = as[rb + gid][kk + tig + 4], a3 = as[rb + gid + 8][kk + tig + 4];
#pragma unroll
                for (int nt = 0; nt < 2; nt++)
                    mma8(acc[mt][nt], a0, a1, a2, a3, bf[nt][0], bf[nt][1]);
            }
        }
        __syncthreads();
    }
#pragma unroll
    for (int mt = 0; mt < 2; mt++) {
#pragma unroll
        for (int nt = 0; nt < 2; nt++) {
            int r0 = mb + mw * 32 + mt * 16 + gid;
            int c0 = nb + nw * 16 + nt * 8 + 2 * tig;
            out[(size_t)r0 * VV + c0] = acc[mt][nt][0] + bias[c0];
            out[(size_t)r0 * VV + c0 + 1] = acc[mt][nt][1] + bias[c0 + 1];
            out[(size_t)(r0 + 8) * VV + c0] = acc[mt][nt][2] + bias[c0];
            out[(size_t)(r0 + 8) * VV + c0 + 1] = acc[mt][nt][3] + bias[c0 + 1];
        }
    }
}

// ---------------- launch ----------------
extern "C" void kernel_launch(void* const* d_in, const int* in_sizes, int n_in,
                              void* d_out, int out_size) {
    (void)in_sizes; (void)n_in; (void)out_size;
    const int* obs = (const int*)d_in[0];
    const float* hidden_init = (const float*)d_in[1];
    const float* kinit = (const float*)d_in[2];
    const float* vinit = (const float*)d_in[3];
    const float* enc_w = (const float*)d_in[4];
    const float* q_w = (const float*)d_in[5];
    const float* q_b = (const float*)d_in[6];
    const float* qn_g = (const float*)d_in[7];
    const float* qn_b = (const float*)d_in[8];
    const float* int_w = (const float*)d_in[9];
    const float* int_b = (const float*)d_in[10];
    const float* intn_g = (const float*)d_in[11];
    const float* intn_b = (const float*)d_in[12];
    const float* fin_w = (const float*)d_in[13];
    const float* fin_b = (const float*)d_in[14];
    const float* fn_g = (const float*)d_in[15];
    const float* fn_b = (const float*)d_in[16];
    const float* dec_w = (const float*)d_in[17];
    const float* dec_b = (const float*)d_in[18];

    float* logits = (float*)d_out;
    float* states_full = logits + (size_t)SS * BB * VV;

    k_init<<<BB, 256>>>(hidden_init, kinit, vinit, states_full);
    k_embed<<<SS * BB, 256>>>(obs, enc_w);

    for (int s = 0; s < SS; s++) {
        // q = relu(ln([e,hidden] @ q_w.T + q_b))
        k_gemm_step<<<dim3(16, 4), 256>>>(s, 0, q_w, 2048, 512, 1024, 0);
        k_ln_q_attn<<<BB, 256>>>(q_b, qn_g, qn_b, s);
        // inter = relu(ln([e,q,attn,hidden] @ int_w.T + int_b))  (x order [e,hidden,q,attn], cols permuted)
        k_gemm_step<<<dim3(64, 4), 256>>>(s, 0, int_w, 4096, 1024, 4096, 1);
        k_ln_int<<<BB, 256>>>(int_b, intn_g, intn_b);
        // final = relu(ln(inter @ fin_w.T + fin_b)) -> split k,v,h
        k_gemm_step<<<dim3(48, 4), 256>>>(-1, 1, fin_w, 4096, 1024, 3072, 0);
        k_ln_fin<<<BB, 256>>>(fin_b, fn_g, fn_b, s, states_full);
    }

    // logits = states @ dec_w.T + dec_b   (states = states_full rows 1..S)
    k_dec<<<dim3(VV / 64, (SS * BB) / 64), 256>>>(states_full + BB * NHID, dec_w, dec_b, logits);
}

// round 4
// speedup vs baseline: 4.3273x; 4.3273x over previous
#include <cuda_runtime.h>
#include <math.h>

#define SS 128
#define BB 32
#define VV 32000
#define NINP 1024
#define NHID 1024
#define NHEADS 16
#define HD 64
#define KSPLIT 8

// ---------------- device scratch (no runtime allocs allowed) ----------------
static __device__ float g_emb[(size_t)SS * BB * NINP];       // raw fp32 embeddings
static __device__ float g_xbuf[BB * 3072];                   // [hidden|q|attn] fp32
static __device__ float g_kcache[(size_t)(SS + 1) * BB * NHID];
static __device__ float g_vcache[(size_t)(SS + 1) * BB * NHID];
static __device__ float g_inter[BB * 4096];
static __device__ float g_part[KSPLIT * BB * 4096];          // split-K partials

// ---------------- helpers ----------------
__device__ __forceinline__ unsigned packbf(float e, float o) {
    // word = {lo16 = bf16(e), hi16 = bf16(o)}
    unsigned r;
    asm("cvt.rn.bf16x2.f32 %0, %1, %2;" : "=r"(r) : "f"(o), "f"(e));
    return r;
}

// fp32x4 (4 consecutive k) -> 2 hi words + 2 lo words (bf16 pair split)
__device__ __forceinline__ void cvtpair(float4 v, unsigned* ph, unsigned* pl) {
    unsigned h0 = packbf(v.x, v.y);
    unsigned h1 = packbf(v.z, v.w);
    float r0 = v.x - __uint_as_float(h0 << 16);
    float r1 = v.y - __uint_as_float(h0 & 0xffff0000u);
    float r2 = v.z - __uint_as_float(h1 << 16);
    float r3 = v.w - __uint_as_float(h1 & 0xffff0000u);
    ph[0] = h0; ph[1] = h1;
    pl[0] = packbf(r0, r1);
    pl[1] = packbf(r2, r3);
}

__device__ __forceinline__ void mmabf(float* c, unsigned a0, unsigned a1, unsigned a2,
                                      unsigned a3, unsigned b0, unsigned b1) {
    asm volatile(
        "mma.sync.aligned.m16n8k16.row.col.f32.bf16.bf16.f32 "
        "{%0,%1,%2,%3},{%4,%5,%6,%7},{%8,%9},{%0,%1,%2,%3};"
        : "+f"(c[0]), "+f"(c[1]), "+f"(c[2]), "+f"(c[3])
        : "r"(a0), "r"(a1), "r"(a2), "r"(a3), "r"(b0), "r"(b1));
}

__device__ __forceinline__ void bred2(float& s1, float& s2, float* r1, float* r2, int nw) {
    int lane = threadIdx.x & 31, wid = threadIdx.x >> 5;
#pragma unroll
    for (int o = 16; o; o >>= 1) {
        s1 += __shfl_xor_sync(0xffffffffu, s1, o);
        s2 += __shfl_xor_sync(0xffffffffu, s2, o);
    }
    if (lane == 0) { r1[wid] = s1; r2[wid] = s2; }
    __syncthreads();
    s1 = 0.f; s2 = 0.f;
    for (int i = 0; i < nw; i++) { s1 += r1[i]; s2 += r2[i]; }
}

// ---------------- setup ----------------
__global__ void k_init(const float* __restrict__ h0, const float* __restrict__ kc0,
                       const float* __restrict__ vc0, float* __restrict__ states_full) {
    int b = blockIdx.x, t = threadIdx.x;
    float4 h = ((const float4*)(h0 + b * NHID))[t];
    ((float4*)(g_xbuf + b * 3072))[t] = h;
    ((float4*)(states_full + (size_t)b * NHID))[t] = h;
    ((float4*)(g_kcache + (size_t)b * NHID))[t] = ((const float4*)(kc0 + b * NHID))[t];
    ((float4*)(g_vcache + (size_t)b * NHID))[t] = ((const float4*)(vc0 + b * NHID))[t];
}

__global__ void k_embed(const int* __restrict__ obs, const float* __restrict__ enc_w) {
    int idx = blockIdx.x;  // s*B + b
    int row = obs[idx];
    ((float4*)(g_emb + (size_t)idx * NINP))[threadIdx.x] =
        ((const float4*)(enc_w + (size_t)row * NINP))[threadIdx.x];
}

// ---------------- step GEMM: part[b,n] = sum_k x[b,k]*W[n,k], M=32, N-tile=64, splitK=8 ----
// x: cols [0,ecols) from g_emb step row; rest from xr (g_xbuf or g_inter)
__global__ __launch_bounds__(256) void k_gemm_step(int estep, int xsel,
                                                   const float* __restrict__ W,
                                                   int K, int klen, int N, int permute) {
    __shared__ unsigned xh[32][36], xl[32][36], wh[64][36], wl[64][36];
    const int tid = threadIdx.x;
    const int nb = blockIdx.x * 64;
    const int k0 = blockIdx.y * klen;
    const int w = tid >> 5, lane = tid & 31, g = lane >> 2, tig = lane & 3;

    const float* xe = g_emb + (size_t)(estep > 0 ? estep : 0) * BB * NINP;
    const int ecols = (estep >= 0) ? NINP : 0;
    const float* xr = xsel ? g_inter : g_xbuf;
    const int xstride = xsel ? 4096 : 3072;

    float acc[2][4] = {};
    float4 xa[2], wa[4];

    auto loadx = [&](int kc) {
#pragma unroll
        for (int i = 0; i < 2; i++) {
            int e = tid + i * 256;
            int r = e >> 4, cg = (e & 15) << 2;
            int gc = kc + cg;
            const float* src = (gc < ecols) ? (xe + r * NINP + gc)
                                            : (xr + r * xstride + (gc - ecols));
            xa[i] = *(const float4*)src;
        }
#pragma unroll
        for (int i = 0; i < 4; i++) {
            int e = tid + i * 256;
            int r = e >> 4, cg = (e & 15) << 2;
            int gc = kc + cg;
            int wc = gc;
            if (permute) wc = (gc < 1024) ? gc : ((gc < 2048) ? gc + 2048 : gc - 1024);
            wa[i] = *(const float4*)(W + (size_t)(nb + r) * K + wc);
        }
    };
    auto store = [&]() {
#pragma unroll
        for (int i = 0; i < 2; i++) {
            int e = tid + i * 256;
            int r = e >> 4, wd = (e & 15) * 2;
            cvtpair(xa[i], &xh[r][wd], &xl[r][wd]);
        }
#pragma unroll
        for (int i = 0; i < 4; i++) {
            int e = tid + i * 256;
            int r = e >> 4, wd = (e & 15) * 2;
            cvtpair(wa[i], &wh[r][wd], &wl[r][wd]);
        }
    };

    const int nchunks = klen >> 6;
    loadx(k0);
    for (int c = 0; c < nchunks; c++) {
        store();
        __syncthreads();
        if (c + 1 < nchunks) loadx(k0 + (c + 1) * 64);
#pragma unroll
        for (int s = 0; s < 4; s++) {
            int w0 = s * 8 + tig, w1 = w0 + 4;
            unsigned bh0 = wh[w * 8 + g][w0], bh1 = wh[w * 8 + g][w1];
            unsigned bl0 = wl[w * 8 + g][w0], bl1 = wl[w * 8 + g][w1];
#pragma unroll
            for (int mt = 0; mt < 2; mt++) {
                int r0 = mt * 16 + g;
                unsigned ah0 = xh[r0][w0], ah1 = xh[r0 + 8][w0];
                unsigned ah2 = xh[r0][w1], ah3 = xh[r0 + 8][w1];
                unsigned al0 = xl[r0][w0], al1 = xl[r0 + 8][w0];
                unsigned al2 = xl[r0][w1], al3 = xl[r0 + 8][w1];
                mmabf(acc[mt], ah0, ah1, ah2, ah3, bh0, bh1);
                mmabf(acc[mt], ah0, ah1, ah2, ah3, bl0, bl1);
                mmabf(acc[mt], al0, al1, al2, al3, bh0, bh1);
            }
        }
        __syncthreads();
    }
    float* p = g_part + (size_t)blockIdx.y * 32 * N;
    int n0 = nb + w * 8 + 2 * tig;
#pragma unroll
    for (int mt = 0; mt < 2; mt++) {
        int r0 = mt * 16 + g;
        *(float2*)&p[r0 * N + n0] = make_float2(acc[mt][0], acc[mt][1]);
        *(float2*)&p[(r0 + 8) * N + n0] = make_float2(acc[mt][2], acc[mt][3]);
    }
}

// ---------------- fused LN(q)+relu + single-head attention; grid (B, NHEADS) ----------------
__global__ __launch_bounds__(128) void k_attn(const float* __restrict__ qb,
                                              const float* __restrict__ gg,
                                              const float* __restrict__ bbv, int step) {
    __shared__ float qh[64];
    __shared__ float sc[132];
    __shared__ float red1[4], red2[4];
    __shared__ float osum[64];
    int b = blockIdx.x, h = blockIdx.y, tid = threadIdx.x;
    int lane = tid & 31, wid = tid >> 5;

    // LN stats over all 1024 cols (thread t owns cols [t*8, t*8+8))
    float pre[8];
    float s1 = 0.f, s2 = 0.f;
#pragma unroll
    for (int i = 0; i < 2; i++) {
        int c = tid * 8 + i * 4;
        float4 v = *(const float4*)&qb[c];
#pragma unroll
        for (int j = 0; j < KSPLIT; j++) {
            float4 p = *(const float4*)&g_part[(size_t)j * 32 * 1024 + b * 1024 + c];
            v.x += p.x; v.y += p.y; v.z += p.z; v.w += p.w;
        }
        pre[i * 4 + 0] = v.x; pre[i * 4 + 1] = v.y; pre[i * 4 + 2] = v.z; pre[i * 4 + 3] = v.w;
        s1 += v.x + v.y + v.z + v.w;
        s2 += v.x * v.x + v.y * v.y + v.z * v.z + v.w * v.w;
    }
    bred2(s1, s2, red1, red2, 4);
    float mu = s1 * (1.f / 1024.f);
    float rstd = rsqrtf(s2 * (1.f / 1024.f) - mu * mu + 1e-5f);
#pragma unroll
    for (int i = 0; i < 8; i++) {
        int c = tid * 8 + i;
        float q = fmaxf((pre[i] - mu) * rstd * gg[c] + bbv[c], 0.f);
        g_xbuf[b * 3072 + 1024 + c] = q;  // all head-blocks write identical values: benign
        if ((c >> 6) == h) qh[c & 63] = q;
    }
    __syncthreads();

    // scores over cache positions 0..step
    int L = step + 1;
    for (int c = tid; c < L; c += 128) {
        const float* kr = g_kcache + ((size_t)c * BB + b) * NHID + h * HD;
        float d = 0.f;
#pragma unroll
        for (int j = 0; j < 16; j++) {
            float4 kv = *(const float4*)&kr[j * 4];
            d += qh[j * 4] * kv.x + qh[j * 4 + 1] * kv.y +
                 qh[j * 4 + 2] * kv.z + qh[j * 4 + 3] * kv.w;
        }
        sc[c] = d * 0.125f;
    }
    float m = -1e30f;
    for (int c = tid; c < L; c += 128) m = fmaxf(m, sc[c]);
#pragma unroll
    for (int o = 16; o; o >>= 1) m = fmaxf(m, __shfl_xor_sync(0xffffffffu, m, o));
    if (lane == 0) red1[wid] = m;
    __syncthreads();
    m = fmaxf(fmaxf(red1[0], red1[1]), fmaxf(red1[2], red1[3]));
    float se = 0.f;
    for (int c = tid; c < L; c += 128) {
        float e = expf(sc[c] - m);
        sc[c] = e;
        se += e;
    }
#pragma unroll
    for (int o = 16; o; o >>= 1) se += __shfl_xor_sync(0xffffffffu, se, o);
    if (lane == 0) red2[wid] = se;
    __syncthreads();
    se = red2[0] + red2[1] + red2[2] + red2[3];

    // weighted V sum
    int d = tid & 63, cg = tid >> 6;
    float a = 0.f;
    for (int c = cg; c < L; c += 2)
        a += sc[c] * g_vcache[((size_t)c * BB + b) * NHID + h * HD + d];
    if (cg == 1) osum[d] = a;
    __syncthreads();
    if (cg == 0) g_xbuf[b * 3072 + 2048 + h * HD + d] = (a + osum[d]) / se;
}

// ---------------- LN(int)+relu -> g_inter ----------------
__global__ __launch_bounds__(256) void k_ln_int(const float* __restrict__ bias,
                                                const float* __restrict__ gg,
                                                const float* __restrict__ bb2) {
    __shared__ float pre[4096];
    __shared__ float red1[8], red2[8];
    int b = blockIdx.x, tid = threadIdx.x;
    float s1 = 0.f, s2 = 0.f;
#pragma unroll
    for (int i = 0; i < 4; i++) {
        int c = (tid + i * 256) * 4;
        float4 v = *(const float4*)&bias[c];
#pragma unroll
        for (int j = 0; j < KSPLIT; j++) {
            float4 p = *(const float4*)&g_part[(size_t)j * 32 * 4096 + b * 4096 + c];
            v.x += p.x; v.y += p.y; v.z += p.z; v.w += p.w;
        }
        *(float4*)&pre[c] = v;
        s1 += v.x + v.y + v.z + v.w;
        s2 += v.x * v.x + v.y * v.y + v.z * v.z + v.w * v.w;
    }
    bred2(s1, s2, red1, red2, 8);
    float mu = s1 * (1.f / 4096.f);
    float rstd = rsqrtf(s2 * (1.f / 4096.f) - mu * mu + 1e-5f);
#pragma unroll
    for (int i = 0; i < 16; i++) {
        int c = tid + i * 256;
        g_inter[b * 4096 + c] = fmaxf((pre[c] - mu) * rstd * gg[c] + bb2[c], 0.f);
    }
}

// ---------------- LN(fin)+relu -> kcache[i+1], vcache[i+1], hidden/states ----------------
__global__ __launch_bounds__(256) void k_ln_fin(const float* __restrict__ bias,
                                                const float* __restrict__ gg,
                                                const float* __restrict__ bb2, int step,
                                                float* __restrict__ states_full) {
    __shared__ float pre[3072];
    __shared__ float red1[8], red2[8];
    int b = blockIdx.x, tid = threadIdx.x;
    float s1 = 0.f, s2 = 0.f;
#pragma unroll
    for (int i = 0; i < 3; i++) {
        int c = (tid + i * 256) * 4;
        float4 v = *(const float4*)&bias[c];
#pragma unroll
        for (int j = 0; j < KSPLIT; j++) {
            float4 p = *(const float4*)&g_part[(size_t)j * 32 * 3072 + b * 3072 + c];
            v.x += p.x; v.y += p.y; v.z += p.z; v.w += p.w;
        }
        *(float4*)&pre[c] = v;
        s1 += v.x + v.y + v.z + v.w;
        s2 += v.x * v.x + v.y * v.y + v.z * v.z + v.w * v.w;
    }
    bred2(s1, s2, red1, red2, 8);
    float mu = s1 * (1.f / 3072.f);
    float rstd = rsqrtf(s2 * (1.f / 3072.f) - mu * mu + 1e-5f);
#pragma unroll
    for (int i = 0; i < 12; i++) {
        int c = tid + i * 256;
        float y = fmaxf((pre[c] - mu) * rstd * gg[c] + bb2[c], 0.f);
        if (c < 1024) {
            g_kcache[((size_t)(step + 1) * BB + b) * NHID + c] = y;
        } else if (c < 2048) {
            g_vcache[((size_t)(step + 1) * BB + b) * NHID + (c - 1024)] = y;
        } else {
            int d = c - 2048;
            states_full[((size_t)(step + 1) * BB + b) * NHID + d] = y;
            g_xbuf[b * 3072 + d] = y;
        }
    }
}

// ---------------- decoder GEMM: logits[r,n] = states[r,:]@dec_w[n,:] + dec_b[n] ------------
// 128x128 tile per block, bf16-pair 3-term, m-fastest grid for dec_w L2 reuse
__global__ __launch_bounds__(256, 1) void k_dec(const float* __restrict__ A,
                                                const float* __restrict__ Wd,
                                                const float* __restrict__ bias,
                                                float* __restrict__ out) {
    __shared__ unsigned ah[128][20], al[128][20], wwh[128][20], wwl[128][20];
    int tid = threadIdx.x;
    int mb = blockIdx.x * 128, nb = blockIdx.y * 128;
    int w = tid >> 5, lane = tid & 31, g = lane >> 2, tig = lane & 3;
    int mw = w >> 2, nw = w & 3;  // 2 m-warps x 4 n-warps
    float acc[4][4][4] = {};
    float4 aa[4], wv[4];

    auto load = [&](int kc) {
#pragma unroll
        for (int i = 0; i < 4; i++) {
            int e = tid + i * 256;
            int r = e >> 3, cg = (e & 7) << 2;
            aa[i] = *(const float4*)(A + (size_t)(mb + r) * 1024 + kc + cg);
            wv[i] = *(const float4*)(Wd + (size_t)(nb + r) * 1024 + kc + cg);
        }
    };
    auto store = [&]() {
#pragma unroll
        for (int i = 0; i < 4; i++) {
            int e = tid + i * 256;
            int r = e >> 3, wd = (e & 7) * 2;
            cvtpair(aa[i], &ah[r][wd], &al[r][wd]);
            cvtpair(wv[i], &wwh[r][wd], &wwl[r][wd]);
        }
    };

    load(0);
    for (int c = 0; c < 32; c++) {
        store();
        __syncthreads();
        if (c < 31) load((c + 1) * 32);
#pragma unroll
        for (int s = 0; s < 2; s++) {
            int w0 = s * 8 + tig, w1 = w0 + 4;
            unsigned bh[4][2], bl[4][2];
#pragma unroll
            for (int nt = 0; nt < 4; nt++) {
                int col = nw * 32 + nt * 8 + g;
                bh[nt][0] = wwh[col][w0]; bh[nt][1] = wwh[col][w1];
                bl[nt][0] = wwl[col][w0]; bl[nt][1] = wwl[col][w1];
            }
#pragma unroll
            for (int mt = 0; mt < 4; mt++) {
                int r0 = mw * 64 + mt * 16 + g;
                unsigned a0 = ah[r0][w0], a1 = ah[r0 + 8][w0], a2 = ah[r0][w1], a3 = ah[r0 + 8][w1];
                unsigned l0 = al[r0][w0], l1 = al[r0 + 8][w0], l2 = al[r0][w1], l3 = al[r0 + 8][w1];
#pragma unroll
                for (int nt = 0; nt < 4; nt++) {
                    mmabf(acc[mt][nt], a0, a1, a2, a3, bh[nt][0], bh[nt][1]);
                    mmabf(acc[mt][nt], a0, a1, a2, a3, bl[nt][0], bl[nt][1]);
                    mmabf(acc[mt][nt], l0, l1, l2, l3, bh[nt][0], bh[nt][1]);
                }
            }
        }
        __syncthreads();
    }
#pragma unroll
    for (int mt = 0; mt < 4; mt++) {
        int r0 = mb + mw * 64 + mt * 16 + g;
#pragma unroll
        for (int nt = 0; nt < 4; nt++) {
            int c0 = nb + nw * 32 + nt * 8 + 2 * tig;
            float2 bv = *(const float2*)&bias[c0];
            *(float2*)&out[(size_t)r0 * VV + c0] =
                make_float2(acc[mt][nt][0] + bv.x, acc[mt][nt][1] + bv.y);
            *(float2*)&out[(size_t)(r0 + 8) * VV + c0] =
                make_float2(acc[mt][nt][2] + bv.x, acc[mt][nt][3] + bv.y);
        }
    }
}

// ---------------- launch ----------------
extern "C" void kernel_launch(void* const* d_in, const int* in_sizes, int n_in,
                              void* d_out, int out_size) {
    (void)in_sizes; (void)n_in; (void)out_size;
    const int* obs = (const int*)d_in[0];
    const float* hidden_init = (const float*)d_in[1];
    const float* kinit = (const float*)d_in[2];
    const float* vinit = (const float*)d_in[3];
    const float* enc_w = (const float*)d_in[4];
    const float* q_w = (const float*)d_in[5];
    const float* q_b = (const float*)d_in[6];
    const float* qn_g = (const float*)d_in[7];
    const float* qn_b = (const float*)d_in[8];
    const float* int_w = (const float*)d_in[9];
    const float* int_b = (const float*)d_in[10];
    const float* intn_g = (const float*)d_in[11];
    const float* intn_b = (const float*)d_in[12];
    const float* fin_w = (const float*)d_in[13];
    const float* fin_b = (const float*)d_in[14];
    const float* fn_g = (const float*)d_in[15];
    const float* fn_b = (const float*)d_in[16];
    const float* dec_w = (const float*)d_in[17];
    const float* dec_b = (const float*)d_in[18];

    float* logits = (float*)d_out;
    float* states_full = logits + (size_t)SS * BB * VV;

    k_init<<<BB, 256>>>(hidden_init, kinit, vinit, states_full);
    k_embed<<<SS * BB, 256>>>(obs, enc_w);

    for (int s = 0; s < SS; s++) {
        // q = relu(ln([e,hidden] @ q_w.T + q_b))
        k_gemm_step<<<dim3(16, KSPLIT), 256>>>(s, 0, q_w, 2048, 2048 / KSPLIT, 1024, 0);
        k_attn<<<dim3(BB, NHEADS), 128>>>(q_b, qn_g, qn_b, s);
        // inter = relu(ln([e,q,attn,hidden] @ int_w.T + int_b)); x order [e,hidden,q,attn]
        k_gemm_step<<<dim3(64, KSPLIT), 256>>>(s, 0, int_w, 4096, 4096 / KSPLIT, 4096, 1);
        k_ln_int<<<BB, 256>>>(int_b, intn_g, intn_b);
        // final = relu(ln(inter @ fin_w.T + fin_b)) -> split k,v,h
        k_gemm_step<<<dim3(48, KSPLIT), 256>>>(-1, 1, fin_w, 4096, 4096 / KSPLIT, 3072, 0);
        k_ln_fin<<<BB, 256>>>(fin_b, fn_g, fn_b, s, states_full);
    }

    // logits = states @ dec_w.T + dec_b  (states = states_full rows 1..S)
    k_dec<<<dim3(32, VV / 128), 256>>>(states_full + BB * NHID, dec_w, dec_b, logits);
}